// round 5
// baseline (speedup 1.0000x reference)
#include <cuda_runtime.h>
#include <cuda_bf16.h>
#include <cstdint>

// ---------------------------------------------------------------------------
// GATNet, round 5:
//  - CSR-by-destination edge pipeline
//  - layer-2 algebraic refactor (aggregate hact, then GEMM by permuted W2)
//  - bf16 3-way split tensor GEMM, now register-prefetch pipelined
//  - build_wa parallelized (warp per output)
// Output layout: [ out (N*64) | embeddings (N*128) ]
// ---------------------------------------------------------------------------

#define MAXN 100000
#define MAXE 600000
#define MAXET (MAXE + MAXN)

// -------------------- scratch (device globals; no allocs) ------------------
__device__ float g_h1[(size_t)MAXN * 128];    // GEMM1 output
__device__ float g_hact[(size_t)MAXN * 128];  // layer-1 activated output
__device__ float g_aggn[(size_t)MAXN * 512];  // layer-2 normalized aggregate
__device__ float g_as[(size_t)MAXN * 4];
__device__ float g_ad[(size_t)MAXN * 4];
__device__ float g_esum[(size_t)MAXN * 4];
__device__ int   g_cnt[MAXN];
__device__ int   g_off[MAXN + 1];
__device__ int   g_bsum[1024];
__device__ int   g_csrc[MAXET];
__device__ float g_alpha[(size_t)MAXET * 4];
// pre-split / transposed weights (bf16 hi/lo), layout [N][K]
__device__ __nv_bfloat16 g_W1h[128 * 512],  g_W1l[128 * 512];
__device__ __nv_bfloat16 g_W2h[128 * 512],  g_W2l[128 * 512];   // permuted W2
__device__ __nv_bfloat16 g_WLh[64 * 128],   g_WLl[64 * 128];
__device__ float g_was[128 * 4], g_wad[128 * 4];                // W2·a_{src,dst}2

// -------------------- bf16 mma helper ---------------------------------------
__device__ __forceinline__ void mma16816(float* c, const uint32_t* a, const uint32_t* b) {
    asm volatile(
        "mma.sync.aligned.m16n8k16.row.col.f32.bf16.bf16.f32 "
        "{%0,%1,%2,%3}, {%4,%5,%6,%7}, {%8,%9}, {%0,%1,%2,%3};\n"
        : "+f"(c[0]), "+f"(c[1]), "+f"(c[2]), "+f"(c[3])
        : "r"(a[0]), "r"(a[1]), "r"(a[2]), "r"(a[3]), "r"(b[0]), "r"(b[1]));
}

// -------------------- tensor GEMM: C[M,N] = A[M,K] @ B[K,N] (+bias) --------
// A fp32 in gmem (split to bf16 hi/lo on the fly); B pre-split+transposed
// bf16 [N][K]. Tile 128x128, BK=32, 256 threads = 8 warps (2x4 warp grid).
// 3-way split: Ahi*Bhi + Ahi*Blo + Alo*Bhi.
// Register-prefetch pipeline: next tile's LDGs issue before the MMA loop.
__global__ __launch_bounds__(256) void gemm_bf16x3(
    const float* __restrict__ A,
    const __nv_bfloat16* __restrict__ Bth, const __nv_bfloat16* __restrict__ Btl,
    const float* __restrict__ bias, float* __restrict__ C,
    int M, int N, int K)
{
    __shared__ __nv_bfloat16 Ah[128][40];
    __shared__ __nv_bfloat16 Al[128][40];
    __shared__ __nv_bfloat16 Bh[128][40];
    __shared__ __nv_bfloat16 Bl[128][40];

    const int tid  = threadIdx.x;
    const int lane = tid & 31;
    const int wid  = tid >> 5;
    const int brow = blockIdx.y * 128;
    const int bcol = blockIdx.x * 128;
    const int moff = (wid >> 2) * 64;
    const int noff = (wid & 3) * 32;

    float acc[4][4][4];
#pragma unroll
    for (int i = 0; i < 4; i++)
#pragma unroll
        for (int j = 0; j < 4; j++)
#pragma unroll
            for (int q = 0; q < 4; q++) acc[i][j][q] = 0.f;

    const int ar  = tid >> 1;
    const int ac  = (tid & 1) * 16;
    const int agr = min(brow + ar, M - 1);
    const int bn  = tid >> 1;
    const int bk  = (tid & 1) * 16;
    const bool bvalid = (bcol + bn) < N;

    const float* aptr = A + (size_t)agr * K + ac;
    const __nv_bfloat16* bph0 = Bth + (size_t)(bcol + bn) * K + bk;
    const __nv_bfloat16* bpl0 = Btl + (size_t)(bcol + bn) * K + bk;

    float4 avr[4];
    uint4  bhr[2], blr[2];

    // prologue: load tile 0
    {
        avr[0] = reinterpret_cast<const float4*>(aptr)[0];
        avr[1] = reinterpret_cast<const float4*>(aptr)[1];
        avr[2] = reinterpret_cast<const float4*>(aptr)[2];
        avr[3] = reinterpret_cast<const float4*>(aptr)[3];
        if (bvalid) {
            bhr[0] = reinterpret_cast<const uint4*>(bph0)[0];
            bhr[1] = reinterpret_cast<const uint4*>(bph0)[1];
            blr[0] = reinterpret_cast<const uint4*>(bpl0)[0];
            blr[1] = reinterpret_cast<const uint4*>(bpl0)[1];
        } else {
            uint4 z = make_uint4(0, 0, 0, 0);
            bhr[0] = bhr[1] = blr[0] = blr[1] = z;
        }
    }

    for (int k0 = 0; k0 < K; k0 += 32) {
        // ---- split + store staged tile to smem ----
        {
            float av[16] = {avr[0].x, avr[0].y, avr[0].z, avr[0].w,
                            avr[1].x, avr[1].y, avr[1].z, avr[1].w,
                            avr[2].x, avr[2].y, avr[2].z, avr[2].w,
                            avr[3].x, avr[3].y, avr[3].z, avr[3].w};
#pragma unroll
            for (int i = 0; i < 16; i += 2) {
                __nv_bfloat16 h0 = __float2bfloat16(av[i]);
                __nv_bfloat16 h1 = __float2bfloat16(av[i + 1]);
                __nv_bfloat16 l0 = __float2bfloat16(av[i]     - __bfloat162float(h0));
                __nv_bfloat16 l1 = __float2bfloat16(av[i + 1] - __bfloat162float(h1));
                __nv_bfloat162 ph; ph.x = h0; ph.y = h1;
                __nv_bfloat162 pl; pl.x = l0; pl.y = l1;
                *reinterpret_cast<__nv_bfloat162*>(&Ah[ar][ac + i]) = ph;
                *reinterpret_cast<__nv_bfloat162*>(&Al[ar][ac + i]) = pl;
            }
            *reinterpret_cast<uint4*>(&Bh[bn][bk])     = bhr[0];
            *reinterpret_cast<uint4*>(&Bh[bn][bk + 8]) = bhr[1];
            *reinterpret_cast<uint4*>(&Bl[bn][bk])     = blr[0];
            *reinterpret_cast<uint4*>(&Bl[bn][bk + 8]) = blr[1];
        }
        __syncthreads();

        // ---- prefetch next tile (LDGs in flight during MMA loop) ----
        if (k0 + 32 < K) {
            const float* ap = aptr + k0 + 32;
            avr[0] = reinterpret_cast<const float4*>(ap)[0];
            avr[1] = reinterpret_cast<const float4*>(ap)[1];
            avr[2] = reinterpret_cast<const float4*>(ap)[2];
            avr[3] = reinterpret_cast<const float4*>(ap)[3];
            if (bvalid) {
                const __nv_bfloat16* bph = bph0 + k0 + 32;
                const __nv_bfloat16* bpl = bpl0 + k0 + 32;
                bhr[0] = reinterpret_cast<const uint4*>(bph)[0];
                bhr[1] = reinterpret_cast<const uint4*>(bph)[1];
                blr[0] = reinterpret_cast<const uint4*>(bpl)[0];
                blr[1] = reinterpret_cast<const uint4*>(bpl)[1];
            }
        }

        // ---- MMA over staged tile ----
#pragma unroll
        for (int ks = 0; ks < 32; ks += 16) {
            const int kf = ks + (lane & 3) * 2;
            uint32_t bhf[4][2], blf[4][2];
#pragma unroll
            for (int in = 0; in < 4; in++) {
                int n = noff + in * 8 + (lane >> 2);
                bhf[in][0] = *reinterpret_cast<const uint32_t*>(&Bh[n][kf]);
                bhf[in][1] = *reinterpret_cast<const uint32_t*>(&Bh[n][kf + 8]);
                blf[in][0] = *reinterpret_cast<const uint32_t*>(&Bl[n][kf]);
                blf[in][1] = *reinterpret_cast<const uint32_t*>(&Bl[n][kf + 8]);
            }
#pragma unroll
            for (int im = 0; im < 4; im++) {
                int m = moff + im * 16 + (lane >> 2);
                uint32_t ahf[4], alf[4];
                ahf[0] = *reinterpret_cast<const uint32_t*>(&Ah[m][kf]);
                ahf[1] = *reinterpret_cast<const uint32_t*>(&Ah[m + 8][kf]);
                ahf[2] = *reinterpret_cast<const uint32_t*>(&Ah[m][kf + 8]);
                ahf[3] = *reinterpret_cast<const uint32_t*>(&Ah[m + 8][kf + 8]);
                alf[0] = *reinterpret_cast<const uint32_t*>(&Al[m][kf]);
                alf[1] = *reinterpret_cast<const uint32_t*>(&Al[m + 8][kf]);
                alf[2] = *reinterpret_cast<const uint32_t*>(&Al[m][kf + 8]);
                alf[3] = *reinterpret_cast<const uint32_t*>(&Al[m + 8][kf + 8]);
#pragma unroll
                for (int in = 0; in < 4; in++) {
                    mma16816(acc[im][in], ahf, bhf[in]);
                    mma16816(acc[im][in], ahf, blf[in]);
                    mma16816(acc[im][in], alf, bhf[in]);
                }
            }
        }
        __syncthreads();
    }

    // ---- epilogue ----
#pragma unroll
    for (int im = 0; im < 4; im++) {
#pragma unroll
        for (int in = 0; in < 4; in++) {
            int gr = brow + moff + im * 16 + (lane >> 2);
            int gc = bcol + noff + in * 8 + (lane & 3) * 2;
            if (gc >= N) continue;
            float bx = bias ? bias[gc] : 0.f;
            float by = bias ? bias[gc + 1] : 0.f;
            if (gr < M) {
                float2 v = make_float2(acc[im][in][0] + bx, acc[im][in][1] + by);
                *reinterpret_cast<float2*>(C + (size_t)gr * N + gc) = v;
            }
            if (gr + 8 < M) {
                float2 v = make_float2(acc[im][in][2] + bx, acc[im][in][3] + by);
                *reinterpret_cast<float2*>(C + (size_t)(gr + 8) * N + gc) = v;
            }
        }
    }
}

// -------------------- weight prep kernels ----------------------------------
__global__ void split_w(const float* __restrict__ W,
                        __nv_bfloat16* __restrict__ hi, __nv_bfloat16* __restrict__ lo,
                        int K, int N)
{
    int idx = blockIdx.x * blockDim.x + threadIdx.x;
    if (idx >= K * N) return;
    int k = idx / N, n = idx % N;
    float v = W[idx];
    __nv_bfloat16 h = __float2bfloat16(v);
    hi[(size_t)n * K + k] = h;
    lo[(size_t)n * K + k] = __float2bfloat16(v - __bfloat162float(h));
}
__global__ void split_w2p(const float* __restrict__ W2)
{
    int idx = blockIdx.x * blockDim.x + threadIdx.x;   // 512*128
    if (idx >= 512 * 128) return;
    int row = idx >> 7, c = idx & 127;
    int h = row >> 7, k = row & 127;
    float v = W2[(size_t)k * 512 + h * 128 + c];
    __nv_bfloat16 hb = __float2bfloat16(v);
    g_W2h[(size_t)c * 512 + row] = hb;
    g_W2l[(size_t)c * 512 + row] = __float2bfloat16(v - __bfloat162float(hb));
}
// warp per (k,h): wa_s[k][h] = sum_c W2[k][h*128+c] * a_src2[h][c]
__global__ void build_wa(const float* __restrict__ W2,
                         const float* __restrict__ as2, const float* __restrict__ ad2)
{
    int gw   = (blockIdx.x * blockDim.x + threadIdx.x) >> 5;   // 0..511
    int lane = threadIdx.x & 31;
    if (gw >= 512) return;
    int k = gw >> 2, h = gw & 3;
    float ss = 0.f, sd = 0.f;
    for (int c = lane; c < 128; c += 32) {
        float w = W2[(size_t)k * 512 + h * 128 + c];
        ss = fmaf(w, as2[h * 128 + c], ss);
        sd = fmaf(w, ad2[h * 128 + c], sd);
    }
#pragma unroll
    for (int o = 16; o; o >>= 1) {
        ss += __shfl_xor_sync(0xFFFFFFFFu, ss, o);
        sd += __shfl_xor_sync(0xFFFFFFFFu, sd, o);
    }
    if (lane == 0) {
        g_was[k * 4 + h] = ss;
        g_wad[k * 4 + h] = sd;
    }
}

// -------------------- CSR build --------------------------------------------
__global__ void zero_cnt(int N) {
    int i = blockIdx.x * blockDim.x + threadIdx.x;
    if (i < N) g_cnt[i] = 0;
}
__global__ void hist_k(const int* __restrict__ dst, int E, int N) {
    int e = blockIdx.x * blockDim.x + threadIdx.x;
    if (e >= E + N) return;
    int d = (e < E) ? dst[e] : e - E;
    atomicAdd(&g_cnt[d], 1);
}
__global__ __launch_bounds__(1024) void scan1(int N) {
    __shared__ int sh[1024];
    int i = blockIdx.x * 1024 + threadIdx.x;
    int v = (i < N) ? g_cnt[i] : 0;
    sh[threadIdx.x] = v;
    __syncthreads();
    for (int o = 1; o < 1024; o <<= 1) {
        int t = (threadIdx.x >= o) ? sh[threadIdx.x - o] : 0;
        __syncthreads();
        sh[threadIdx.x] += t;
        __syncthreads();
    }
    if (i < N) g_off[i] = sh[threadIdx.x] - v;
    if (threadIdx.x == 1023) g_bsum[blockIdx.x] = sh[1023];
}
__global__ __launch_bounds__(1024) void scan2(int NB) {
    __shared__ int sh[1024];
    int v = (threadIdx.x < NB) ? g_bsum[threadIdx.x] : 0;
    sh[threadIdx.x] = v;
    __syncthreads();
    for (int o = 1; o < 1024; o <<= 1) {
        int t = (threadIdx.x >= o) ? sh[threadIdx.x - o] : 0;
        __syncthreads();
        sh[threadIdx.x] += t;
        __syncthreads();
    }
    if (threadIdx.x < NB) g_bsum[threadIdx.x] = sh[threadIdx.x] - v;
}
__global__ void scan3(int N, int Et) {
    int i = blockIdx.x * blockDim.x + threadIdx.x;
    if (i < N) {
        int v = g_off[i] + g_bsum[i >> 10];
        g_off[i] = v;
        g_cnt[i] = v;
    }
    if (i == 0) g_off[N] = Et;
}
__global__ void scatter_k(const int* __restrict__ src, const int* __restrict__ dst,
                          int E, int N) {
    int e = blockIdx.x * blockDim.x + threadIdx.x;
    if (e >= E + N) return;
    int s, d;
    if (e < E) { s = src[e]; d = dst[e]; } else { s = d = e - E; }
    int p = atomicAdd(&g_cnt[d], 1);
    g_csrc[p] = s;
}

// -------------------- layer-1 attention logits ------------------------------
__global__ void alpha_kernel(const float* __restrict__ h,
                             const float* __restrict__ asrc,
                             const float* __restrict__ adst,
                             int N, int C)
{
    int gw   = (blockIdx.x * blockDim.x + threadIdx.x) >> 5;
    int lane = threadIdx.x & 31;
    if (gw >= N * 4) return;
    int n = gw >> 2, hh = gw & 3;
    const float* hv = h + (size_t)n * 4 * C + (size_t)hh * C;
    float s = 0.f, d = 0.f;
    for (int c = lane; c < C; c += 32) {
        float v = hv[c];
        s = fmaf(v, asrc[hh * C + c], s);
        d = fmaf(v, adst[hh * C + c], d);
    }
#pragma unroll
    for (int o = 16; o; o >>= 1) {
        s += __shfl_down_sync(0xFFFFFFFFu, s, o);
        d += __shfl_down_sync(0xFFFFFFFFu, d, o);
    }
    if (lane == 0) { g_as[gw] = s; g_ad[gw] = d; }
}

// -------------------- layer-2 attention logits (deferred via wa) -----------
__global__ void alpha2_kernel(const float* __restrict__ hact, int N)
{
    int gw   = (blockIdx.x * blockDim.x + threadIdx.x) >> 5;
    int lane = threadIdx.x & 31;
    if (gw >= N) return;
    const float* hv = hact + (size_t)gw * 128;
    float s0 = 0.f, s1 = 0.f, s2 = 0.f, s3 = 0.f;
    float d0 = 0.f, d1 = 0.f, d2 = 0.f, d3 = 0.f;
    for (int k = lane; k < 128; k += 32) {
        float v = hv[k];
        float4 ws = *reinterpret_cast<const float4*>(&g_was[k * 4]);
        float4 wd = *reinterpret_cast<const float4*>(&g_wad[k * 4]);
        s0 = fmaf(v, ws.x, s0); s1 = fmaf(v, ws.y, s1);
        s2 = fmaf(v, ws.z, s2); s3 = fmaf(v, ws.w, s3);
        d0 = fmaf(v, wd.x, d0); d1 = fmaf(v, wd.y, d1);
        d2 = fmaf(v, wd.z, d2); d3 = fmaf(v, wd.w, d3);
    }
#pragma unroll
    for (int o = 16; o; o >>= 1) {
        s0 += __shfl_xor_sync(0xFFFFFFFFu, s0, o);
        s1 += __shfl_xor_sync(0xFFFFFFFFu, s1, o);
        s2 += __shfl_xor_sync(0xFFFFFFFFu, s2, o);
        s3 += __shfl_xor_sync(0xFFFFFFFFu, s3, o);
        d0 += __shfl_xor_sync(0xFFFFFFFFu, d0, o);
        d1 += __shfl_xor_sync(0xFFFFFFFFu, d1, o);
        d2 += __shfl_xor_sync(0xFFFFFFFFu, d2, o);
        d3 += __shfl_xor_sync(0xFFFFFFFFu, d3, o);
    }
    if (lane == 0) {
        *reinterpret_cast<float4*>(&g_as[(size_t)gw * 4]) = make_float4(s0, s1, s2, s3);
        *reinterpret_cast<float4*>(&g_ad[(size_t)gw * 4]) = make_float4(d0, d1, d2, d3);
    }
}

// -------------------- per-node warp softmax over incoming edges ------------
__global__ void edge_softmax(int N)
{
    int gw   = (blockIdx.x * blockDim.x + threadIdx.x) >> 5;
    int lane = threadIdx.x & 31;
    if (gw >= N) return;
    int beg = g_off[gw], end = g_off[gw + 1];
    float4 D = *reinterpret_cast<const float4*>(g_ad + (size_t)gw * 4);
    float m0 = -1e30f, m1 = -1e30f, m2 = -1e30f, m3 = -1e30f;
    for (int j = beg + lane; j < end; j += 32) {
        int s = g_csrc[j];
        float4 A = *reinterpret_cast<const float4*>(g_as + (size_t)s * 4);
        float v0 = A.x + D.x, v1 = A.y + D.y, v2 = A.z + D.z, v3 = A.w + D.w;
        v0 = v0 > 0.f ? v0 : 0.2f * v0;
        v1 = v1 > 0.f ? v1 : 0.2f * v1;
        v2 = v2 > 0.f ? v2 : 0.2f * v2;
        v3 = v3 > 0.f ? v3 : 0.2f * v3;
        *reinterpret_cast<float4*>(g_alpha + (size_t)j * 4) = make_float4(v0, v1, v2, v3);
        m0 = fmaxf(m0, v0); m1 = fmaxf(m1, v1);
        m2 = fmaxf(m2, v2); m3 = fmaxf(m3, v3);
    }
#pragma unroll
    for (int o = 16; o; o >>= 1) {
        m0 = fmaxf(m0, __shfl_xor_sync(0xFFFFFFFFu, m0, o));
        m1 = fmaxf(m1, __shfl_xor_sync(0xFFFFFFFFu, m1, o));
        m2 = fmaxf(m2, __shfl_xor_sync(0xFFFFFFFFu, m2, o));
        m3 = fmaxf(m3, __shfl_xor_sync(0xFFFFFFFFu, m3, o));
    }
    float s0 = 0.f, s1 = 0.f, s2 = 0.f, s3 = 0.f;
    for (int j = beg + lane; j < end; j += 32) {
        float4 v = *reinterpret_cast<const float4*>(g_alpha + (size_t)j * 4);
        float x0 = expf(v.x - m0), x1 = expf(v.y - m1);
        float x2 = expf(v.z - m2), x3 = expf(v.w - m3);
        *reinterpret_cast<float4*>(g_alpha + (size_t)j * 4) = make_float4(x0, x1, x2, x3);
        s0 += x0; s1 += x1; s2 += x2; s3 += x3;
    }
#pragma unroll
    for (int o = 16; o; o >>= 1) {
        s0 += __shfl_xor_sync(0xFFFFFFFFu, s0, o);
        s1 += __shfl_xor_sync(0xFFFFFFFFu, s1, o);
        s2 += __shfl_xor_sync(0xFFFFFFFFu, s2, o);
        s3 += __shfl_xor_sync(0xFFFFFFFFu, s3, o);
    }
    if (lane == 0)
        *reinterpret_cast<float4*>(g_esum + (size_t)gw * 4) = make_float4(s0, s1, s2, s3);
}

// -------------------- layer-1 gather aggregate + bias + ELU ----------------
__global__ __launch_bounds__(128) void agg1_k(const float* __restrict__ b1, int N)
{
    int n = blockIdx.x;
    if (n >= N) return;
    int c = threadIdx.x;
    int h = c >> 5;
    int beg = g_off[n], end = g_off[n + 1];
    float r = 1.f / (g_esum[(size_t)n * 4 + h] + 1e-16f);
    float acc = 0.f;
    for (int j = beg; j < end; j++) {
        int s = g_csrc[j];
        float w = g_alpha[(size_t)j * 4 + h];
        acc = fmaf(w, g_h1[(size_t)s * 128 + c], acc);
    }
    float v = acc * r + b1[c];
    g_hact[(size_t)n * 128 + c] = v > 0.f ? v : expm1f(v);
}

// -------------------- layer-2 gather aggregate (of hact), normalized -------
__global__ __launch_bounds__(128) void agg2n_k(int N)
{
    int n = blockIdx.x;
    if (n >= N) return;
    int k = threadIdx.x;
    int beg = g_off[n], end = g_off[n + 1];
    float a0 = 0.f, a1 = 0.f, a2 = 0.f, a3 = 0.f;
    for (int j = beg; j < end; j++) {
        int s = g_csrc[j];
        float4 al = *reinterpret_cast<const float4*>(g_alpha + (size_t)j * 4);
        float v = g_hact[(size_t)s * 128 + k];
        a0 = fmaf(al.x, v, a0); a1 = fmaf(al.y, v, a1);
        a2 = fmaf(al.z, v, a2); a3 = fmaf(al.w, v, a3);
    }
    float4 es = *reinterpret_cast<const float4*>(g_esum + (size_t)n * 4);
    float* o = g_aggn + (size_t)n * 512;
    o[k]       = a0 * (0.25f / (es.x + 1e-16f));
    o[128 + k] = a1 * (0.25f / (es.y + 1e-16f));
    o[256 + k] = a2 * (0.25f / (es.z + 1e-16f));
    o[384 + k] = a3 * (0.25f / (es.w + 1e-16f));
}

// ---------------------------------------------------------------------------
extern "C" void kernel_launch(void* const* d_in, const int* in_sizes, int n_in,
                              void* d_out, int out_size)
{
    const float* x      = (const float*)d_in[0];
    const int*   eidx   = (const int*)d_in[1];     // int32
    const float* W1     = (const float*)d_in[2];
    const float* a_src1 = (const float*)d_in[3];
    const float* a_dst1 = (const float*)d_in[4];
    const float* b1     = (const float*)d_in[5];
    const float* W2     = (const float*)d_in[6];
    const float* a_src2 = (const float*)d_in[7];
    const float* a_dst2 = (const float*)d_in[8];
    const float* b2     = (const float*)d_in[9];
    const float* W_lin  = (const float*)d_in[10];
    const float* b_lin  = (const float*)d_in[11];

    const int N  = in_sizes[0] / 512;   // 100000
    const int E  = in_sizes[1] / 2;     // 600000
    const int Et = E + N;

    const int* src = eidx;
    const int* dst = eidx + E;

    float* out = (float*)d_out;                  // [N, 64]
    float* emb = (float*)d_out + (size_t)N * 64; // [N, 128]

    float* h1;   cudaGetSymbolAddress((void**)&h1,   g_h1);
    float* hact; cudaGetSymbolAddress((void**)&hact, g_hact);
    float* aggn; cudaGetSymbolAddress((void**)&aggn, g_aggn);
    __nv_bfloat16 *w1h, *w1l, *w2h, *w2l, *wlh, *wll;
    cudaGetSymbolAddress((void**)&w1h, g_W1h); cudaGetSymbolAddress((void**)&w1l, g_W1l);
    cudaGetSymbolAddress((void**)&w2h, g_W2h); cudaGetSymbolAddress((void**)&w2l, g_W2l);
    cudaGetSymbolAddress((void**)&wlh, g_WLh); cudaGetSymbolAddress((void**)&wll, g_WLl);

    const int T = 256;
    dim3 gg(1, (N + 127) / 128);

    int blk_e     = (Et + T - 1) / T;
    int blk_n     = (N + T - 1) / T;
    int blk_alpha = (N * 4 * 32 + T - 1) / T;
    int blk_soft  = (N * 32 + T - 1) / T;
    int NB        = (N + 1023) / 1024;

    // ---- weight prep (tiny) ----
    split_w<<<(512 * 128 + T - 1) / T, T>>>(W1, w1h, w1l, 512, 128);
    split_w2p<<<(512 * 128 + T - 1) / T, T>>>(W2);
    split_w<<<(128 * 64 + T - 1) / T, T>>>(W_lin, wlh, wll, 128, 64);
    build_wa<<<64, T>>>(W2, a_src2, a_dst2);

    // ---- CSR build (by destination), reused by both layers ----
    zero_cnt<<<blk_n, T>>>(N);
    hist_k<<<blk_e, T>>>(dst, E, N);
    scan1<<<NB, 1024>>>(N);
    scan2<<<1, 1024>>>(NB);
    scan3<<<blk_n, T>>>(N, Et);
    scatter_k<<<blk_e, T>>>(src, dst, E, N);

    // ---- layer 1 ----
    gemm_bf16x3<<<gg, T>>>(x, w1h, w1l, nullptr, h1, N, 128, 512);
    alpha_kernel<<<blk_alpha, T>>>(h1, a_src1, a_dst1, N, 32);
    edge_softmax<<<blk_soft, T>>>(N);
    agg1_k<<<N, 128>>>(b1, N);

    // ---- layer 2 (deferred W2) ----
    alpha2_kernel<<<blk_soft, T>>>(hact, N);
    edge_softmax<<<blk_soft, T>>>(N);
    agg2n_k<<<N, 128>>>(N);
    gemm_bf16x3<<<gg, T>>>(aggn, w2h, w2l, b2, emb, N, 128, 512);

    // ---- head ----
    gemm_bf16x3<<<gg, T>>>(emb, wlh, wll, b_lin, out, N, 64, 128);
}

// round 6
// speedup vs baseline: 1.1872x; 1.1872x over previous
#include <cuda_runtime.h>
#include <cuda_bf16.h>
#include <cstdint>

// ---------------------------------------------------------------------------
// GATNet, round 6:
//  - CSR-by-destination edge pipeline
//  - layer-2 algebraic refactor (aggregate hact, then GEMM by permuted W2)
//  - bf16 3-way split tensor GEMM: ldmatrix frags + cp.async double buffering
// Output layout: [ out (N*64) | embeddings (N*128) ]
// ---------------------------------------------------------------------------

#define MAXN 100000
#define MAXE 600000
#define MAXET (MAXE + MAXN)
#define PAD 40

// -------------------- scratch (device globals; no allocs) ------------------
__device__ float g_h1[(size_t)MAXN * 128];
__device__ float g_hact[(size_t)MAXN * 128];
__device__ float g_aggn[(size_t)MAXN * 512];
__device__ float g_as[(size_t)MAXN * 4];
__device__ float g_ad[(size_t)MAXN * 4];
__device__ float g_esum[(size_t)MAXN * 4];
__device__ int   g_cnt[MAXN];
__device__ int   g_off[MAXN + 1];
__device__ int   g_bsum[1024];
__device__ int   g_csrc[MAXET];
__device__ float g_alpha[(size_t)MAXET * 4];
__device__ __nv_bfloat16 g_W1h[128 * 512],  g_W1l[128 * 512];
__device__ __nv_bfloat16 g_W2h[128 * 512],  g_W2l[128 * 512];
__device__ __nv_bfloat16 g_WLh[64 * 128],   g_WLl[64 * 128];
__device__ float g_was[128 * 4], g_wad[128 * 4];

// -------------------- asm helpers -------------------------------------------
__device__ __forceinline__ void mma16816(float* c, const uint32_t* a, const uint32_t* b) {
    asm volatile(
        "mma.sync.aligned.m16n8k16.row.col.f32.bf16.bf16.f32 "
        "{%0,%1,%2,%3}, {%4,%5,%6,%7}, {%8,%9}, {%0,%1,%2,%3};\n"
        : "+f"(c[0]), "+f"(c[1]), "+f"(c[2]), "+f"(c[3])
        : "r"(a[0]), "r"(a[1]), "r"(a[2]), "r"(a[3]), "r"(b[0]), "r"(b[1]));
}
__device__ __forceinline__ uint32_t smem_u32(const void* p) {
    return (uint32_t)__cvta_generic_to_shared(p);
}
__device__ __forceinline__ void ldsm4(uint32_t& r0, uint32_t& r1, uint32_t& r2,
                                      uint32_t& r3, uint32_t a) {
    asm volatile("ldmatrix.sync.aligned.m8n8.x4.shared.b16 {%0,%1,%2,%3}, [%4];"
                 : "=r"(r0), "=r"(r1), "=r"(r2), "=r"(r3) : "r"(a));
}
__device__ __forceinline__ void cpa16(uint32_t dst, const void* src, int srcsz) {
    asm volatile("cp.async.cg.shared.global [%0], [%1], 16, %2;"
                 :: "r"(dst), "l"(src), "r"(srcsz));
}
__device__ __forceinline__ void cpa_commit() { asm volatile("cp.async.commit_group;"); }
__device__ __forceinline__ void cpa_wait0()  { asm volatile("cp.async.wait_group 0;" ::: "memory"); }

// -------------------- tensor GEMM: C[M,N] = A[M,K] @ B[K,N] (+bias) --------
// A fp32 (split to bf16 hi/lo on the fly), B pre-split+transposed bf16 [N][K].
// 128x128 tile, BK=32, 256 threads (2x4 warp grid), double-buffered smem,
// cp.async for B, ldmatrix fragment loads. 3-way split products.
__global__ __launch_bounds__(256) void gemm_bf16x3(
    const float* __restrict__ A,
    const __nv_bfloat16* __restrict__ Bth, const __nv_bfloat16* __restrict__ Btl,
    const float* __restrict__ bias, float* __restrict__ C,
    int M, int N, int K)
{
    __shared__ __align__(16) __nv_bfloat16 Ah[2][128][PAD];
    __shared__ __align__(16) __nv_bfloat16 Al[2][128][PAD];
    __shared__ __align__(16) __nv_bfloat16 Bh[2][128][PAD];
    __shared__ __align__(16) __nv_bfloat16 Bl[2][128][PAD];

    const int tid  = threadIdx.x;
    const int lane = tid & 31;
    const int wid  = tid >> 5;
    const int brow = blockIdx.y * 128;
    const int bcol = blockIdx.x * 128;
    const int moff = (wid >> 2) * 64;
    const int noff = (wid & 3) * 32;

    float acc[4][4][4];
#pragma unroll
    for (int i = 0; i < 4; i++)
#pragma unroll
        for (int j = 0; j < 4; j++)
#pragma unroll
            for (int q = 0; q < 4; q++) acc[i][j][q] = 0.f;

    // staging thread mapping
    const int ar  = tid >> 1;
    const int ac  = (tid & 1) * 16;
    const int agr = min(brow + ar, M - 1);
    const float* aptr = A + (size_t)agr * K + ac;
    const int bn  = tid >> 1;
    const int bk  = (tid & 1) * 16;
    const bool bvalid = (bcol + bn) < N;
    const int bsz = bvalid ? 16 : 0;
    const int bnc = bvalid ? (bcol + bn) : 0;
    const __nv_bfloat16* bph0 = Bth + (size_t)bnc * K + bk;
    const __nv_bfloat16* bpl0 = Btl + (size_t)bnc * K + bk;

    // ldmatrix lane addressing
    const int lr = lane & 7;
    const int lj = lane >> 3;
    const int a_ro = ((lj & 1) << 3) + lr;   // + moff + im*16
    const int a_co = ((lj >> 1) << 3);       // + ks
    const int b_ro = ((lj >> 1) << 3) + lr;  // + noff (+16 for pair 1)
    const int b_co = ((lj & 1) << 3);        // + ks

    float4 avr[4];

    // ---- prologue: tile 0 ----
    avr[0] = reinterpret_cast<const float4*>(aptr)[0];
    avr[1] = reinterpret_cast<const float4*>(aptr)[1];
    avr[2] = reinterpret_cast<const float4*>(aptr)[2];
    avr[3] = reinterpret_cast<const float4*>(aptr)[3];
    {
        uint32_t dh = smem_u32(&Bh[0][bn][bk]);
        uint32_t dl = smem_u32(&Bl[0][bn][bk]);
        cpa16(dh, bph0, bsz);      cpa16(dh + 16, bph0 + 8, bsz);
        cpa16(dl, bpl0, bsz);      cpa16(dl + 16, bpl0 + 8, bsz);
        cpa_commit();
    }
    {
        float av[16] = {avr[0].x, avr[0].y, avr[0].z, avr[0].w,
                        avr[1].x, avr[1].y, avr[1].z, avr[1].w,
                        avr[2].x, avr[2].y, avr[2].z, avr[2].w,
                        avr[3].x, avr[3].y, avr[3].z, avr[3].w};
        __nv_bfloat16 hb[16], lb[16];
#pragma unroll
        for (int i = 0; i < 16; i++) {
            hb[i] = __float2bfloat16(av[i]);
            lb[i] = __float2bfloat16(av[i] - __bfloat162float(hb[i]));
        }
        *reinterpret_cast<uint4*>(&Ah[0][ar][ac])     = *reinterpret_cast<uint4*>(hb);
        *reinterpret_cast<uint4*>(&Ah[0][ar][ac + 8]) = *reinterpret_cast<uint4*>(hb + 8);
        *reinterpret_cast<uint4*>(&Al[0][ar][ac])     = *reinterpret_cast<uint4*>(lb);
        *reinterpret_cast<uint4*>(&Al[0][ar][ac + 8]) = *reinterpret_cast<uint4*>(lb + 8);
    }
    cpa_wait0();
    __syncthreads();

    int p = 0;
    for (int k0 = 0; k0 < K; k0 += 32) {
        const bool nxt = (k0 + 32) < K;
        if (nxt) {
            const float* ap = aptr + k0 + 32;
            avr[0] = reinterpret_cast<const float4*>(ap)[0];
            avr[1] = reinterpret_cast<const float4*>(ap)[1];
            avr[2] = reinterpret_cast<const float4*>(ap)[2];
            avr[3] = reinterpret_cast<const float4*>(ap)[3];
            uint32_t dh = smem_u32(&Bh[p ^ 1][bn][bk]);
            uint32_t dl = smem_u32(&Bl[p ^ 1][bn][bk]);
            const __nv_bfloat16* bph = bph0 + k0 + 32;
            const __nv_bfloat16* bpl = bpl0 + k0 + 32;
            cpa16(dh, bph, bsz);      cpa16(dh + 16, bph + 8, bsz);
            cpa16(dl, bpl, bsz);      cpa16(dl + 16, bpl + 8, bsz);
            cpa_commit();
        }

        // ---- MMA over staged tile (ldmatrix frags) ----
#pragma unroll
        for (int ks = 0; ks < 32; ks += 16) {
            uint32_t bhf[4][2], blf[4][2];
            {
                uint32_t a0 = smem_u32(&Bh[p][noff + b_ro][ks + b_co]);
                uint32_t a1 = smem_u32(&Bh[p][noff + 16 + b_ro][ks + b_co]);
                uint32_t a2 = smem_u32(&Bl[p][noff + b_ro][ks + b_co]);
                uint32_t a3 = smem_u32(&Bl[p][noff + 16 + b_ro][ks + b_co]);
                ldsm4(bhf[0][0], bhf[0][1], bhf[1][0], bhf[1][1], a0);
                ldsm4(bhf[2][0], bhf[2][1], bhf[3][0], bhf[3][1], a1);
                ldsm4(blf[0][0], blf[0][1], blf[1][0], blf[1][1], a2);
                ldsm4(blf[2][0], blf[2][1], blf[3][0], blf[3][1], a3);
            }
#pragma unroll
            for (int im = 0; im < 4; im++) {
                uint32_t ahf[4], alf[4];
                uint32_t aa = smem_u32(&Ah[p][moff + im * 16 + a_ro][ks + a_co]);
                uint32_t al_ = smem_u32(&Al[p][moff + im * 16 + a_ro][ks + a_co]);
                ldsm4(ahf[0], ahf[1], ahf[2], ahf[3], aa);
                ldsm4(alf[0], alf[1], alf[2], alf[3], al_);
#pragma unroll
                for (int in = 0; in < 4; in++) {
                    mma16816(acc[im][in], ahf, bhf[in]);
                    mma16816(acc[im][in], ahf, blf[in]);
                    mma16816(acc[im][in], alf, bhf[in]);
                }
            }
        }

        if (nxt) {
            float av[16] = {avr[0].x, avr[0].y, avr[0].z, avr[0].w,
                            avr[1].x, avr[1].y, avr[1].z, avr[1].w,
                            avr[2].x, avr[2].y, avr[2].z, avr[2].w,
                            avr[3].x, avr[3].y, avr[3].z, avr[3].w};
            __nv_bfloat16 hb[16], lb[16];
#pragma unroll
            for (int i = 0; i < 16; i++) {
                hb[i] = __float2bfloat16(av[i]);
                lb[i] = __float2bfloat16(av[i] - __bfloat162float(hb[i]));
            }
            *reinterpret_cast<uint4*>(&Ah[p ^ 1][ar][ac])     = *reinterpret_cast<uint4*>(hb);
            *reinterpret_cast<uint4*>(&Ah[p ^ 1][ar][ac + 8]) = *reinterpret_cast<uint4*>(hb + 8);
            *reinterpret_cast<uint4*>(&Al[p ^ 1][ar][ac])     = *reinterpret_cast<uint4*>(lb);
            *reinterpret_cast<uint4*>(&Al[p ^ 1][ar][ac + 8]) = *reinterpret_cast<uint4*>(lb + 8);
            cpa_wait0();
        }
        __syncthreads();
        p ^= 1;
    }

    // ---- epilogue ----
#pragma unroll
    for (int im = 0; im < 4; im++) {
#pragma unroll
        for (int in = 0; in < 4; in++) {
            int gr = brow + moff + im * 16 + (lane >> 2);
            int gc = bcol + noff + in * 8 + (lane & 3) * 2;
            if (gc >= N) continue;
            float bx = bias ? bias[gc] : 0.f;
            float by = bias ? bias[gc + 1] : 0.f;
            if (gr < M) {
                float2 v = make_float2(acc[im][in][0] + bx, acc[im][in][1] + by);
                *reinterpret_cast<float2*>(C + (size_t)gr * N + gc) = v;
            }
            if (gr + 8 < M) {
                float2 v = make_float2(acc[im][in][2] + bx, acc[im][in][3] + by);
                *reinterpret_cast<float2*>(C + (size_t)(gr + 8) * N + gc) = v;
            }
        }
    }
}

// -------------------- weight prep kernels ----------------------------------
__global__ void split_w(const float* __restrict__ W,
                        __nv_bfloat16* __restrict__ hi, __nv_bfloat16* __restrict__ lo,
                        int K, int N)
{
    int idx = blockIdx.x * blockDim.x + threadIdx.x;
    if (idx >= K * N) return;
    int k = idx / N, n = idx % N;
    float v = W[idx];
    __nv_bfloat16 h = __float2bfloat16(v);
    hi[(size_t)n * K + k] = h;
    lo[(size_t)n * K + k] = __float2bfloat16(v - __bfloat162float(h));
}
__global__ void split_w2p(const float* __restrict__ W2)
{
    int idx = blockIdx.x * blockDim.x + threadIdx.x;
    if (idx >= 512 * 128) return;
    int row = idx >> 7, c = idx & 127;
    int h = row >> 7, k = row & 127;
    float v = W2[(size_t)k * 512 + h * 128 + c];
    __nv_bfloat16 hb = __float2bfloat16(v);
    g_W2h[(size_t)c * 512 + row] = hb;
    g_W2l[(size_t)c * 512 + row] = __float2bfloat16(v - __bfloat162float(hb));
}
__global__ void build_wa(const float* __restrict__ W2,
                         const float* __restrict__ as2, const float* __restrict__ ad2)
{
    int gw   = (blockIdx.x * blockDim.x + threadIdx.x) >> 5;
    int lane = threadIdx.x & 31;
    if (gw >= 512) return;
    int k = gw >> 2, h = gw & 3;
    float ss = 0.f, sd = 0.f;
    for (int c = lane; c < 128; c += 32) {
        float w = W2[(size_t)k * 512 + h * 128 + c];
        ss = fmaf(w, as2[h * 128 + c], ss);
        sd = fmaf(w, ad2[h * 128 + c], sd);
    }
#pragma unroll
    for (int o = 16; o; o >>= 1) {
        ss += __shfl_xor_sync(0xFFFFFFFFu, ss, o);
        sd += __shfl_xor_sync(0xFFFFFFFFu, sd, o);
    }
    if (lane == 0) { g_was[k * 4 + h] = ss; g_wad[k * 4 + h] = sd; }
}

// -------------------- CSR build --------------------------------------------
__global__ void zero_cnt(int N) {
    int i = blockIdx.x * blockDim.x + threadIdx.x;
    if (i < N) g_cnt[i] = 0;
}
__global__ void hist_k(const int* __restrict__ dst, int E, int N) {
    int e = blockIdx.x * blockDim.x + threadIdx.x;
    if (e >= E + N) return;
    int d = (e < E) ? dst[e] : e - E;
    atomicAdd(&g_cnt[d], 1);
}
__global__ __launch_bounds__(1024) void scan1(int N) {
    __shared__ int sh[1024];
    int i = blockIdx.x * 1024 + threadIdx.x;
    int v = (i < N) ? g_cnt[i] : 0;
    sh[threadIdx.x] = v;
    __syncthreads();
    for (int o = 1; o < 1024; o <<= 1) {
        int t = (threadIdx.x >= o) ? sh[threadIdx.x - o] : 0;
        __syncthreads();
        sh[threadIdx.x] += t;
        __syncthreads();
    }
    if (i < N) g_off[i] = sh[threadIdx.x] - v;
    if (threadIdx.x == 1023) g_bsum[blockIdx.x] = sh[1023];
}
__global__ __launch_bounds__(1024) void scan2(int NB) {
    __shared__ int sh[1024];
    int v = (threadIdx.x < NB) ? g_bsum[threadIdx.x] : 0;
    sh[threadIdx.x] = v;
    __syncthreads();
    for (int o = 1; o < 1024; o <<= 1) {
        int t = (threadIdx.x >= o) ? sh[threadIdx.x - o] : 0;
        __syncthreads();
        sh[threadIdx.x] += t;
        __syncthreads();
    }
    if (threadIdx.x < NB) g_bsum[threadIdx.x] = sh[threadIdx.x] - v;
}
__global__ void scan3(int N, int Et) {
    int i = blockIdx.x * blockDim.x + threadIdx.x;
    if (i < N) {
        int v = g_off[i] + g_bsum[i >> 10];
        g_off[i] = v;
        g_cnt[i] = v;
    }
    if (i == 0) g_off[N] = Et;
}
__global__ void scatter_k(const int* __restrict__ src, const int* __restrict__ dst,
                          int E, int N) {
    int e = blockIdx.x * blockDim.x + threadIdx.x;
    if (e >= E + N) return;
    int s, d;
    if (e < E) { s = src[e]; d = dst[e]; } else { s = d = e - E; }
    int p = atomicAdd(&g_cnt[d], 1);
    g_csrc[p] = s;
}

// -------------------- attention logits --------------------------------------
__global__ void alpha_kernel(const float* __restrict__ h,
                             const float* __restrict__ asrc,
                             const float* __restrict__ adst,
                             int N, int C)
{
    int gw   = (blockIdx.x * blockDim.x + threadIdx.x) >> 5;
    int lane = threadIdx.x & 31;
    if (gw >= N * 4) return;
    int n = gw >> 2, hh = gw & 3;
    const float* hv = h + (size_t)n * 4 * C + (size_t)hh * C;
    float s = 0.f, d = 0.f;
    for (int c = lane; c < C; c += 32) {
        float v = hv[c];
        s = fmaf(v, asrc[hh * C + c], s);
        d = fmaf(v, adst[hh * C + c], d);
    }
#pragma unroll
    for (int o = 16; o; o >>= 1) {
        s += __shfl_down_sync(0xFFFFFFFFu, s, o);
        d += __shfl_down_sync(0xFFFFFFFFu, d, o);
    }
    if (lane == 0) { g_as[gw] = s; g_ad[gw] = d; }
}

__global__ void alpha2_kernel(const float* __restrict__ hact, int N)
{
    int gw   = (blockIdx.x * blockDim.x + threadIdx.x) >> 5;
    int lane = threadIdx.x & 31;
    if (gw >= N) return;
    const float* hv = hact + (size_t)gw * 128;
    float s0 = 0.f, s1 = 0.f, s2 = 0.f, s3 = 0.f;
    float d0 = 0.f, d1 = 0.f, d2 = 0.f, d3 = 0.f;
    for (int k = lane; k < 128; k += 32) {
        float v = hv[k];
        float4 ws = *reinterpret_cast<const float4*>(&g_was[k * 4]);
        float4 wd = *reinterpret_cast<const float4*>(&g_wad[k * 4]);
        s0 = fmaf(v, ws.x, s0); s1 = fmaf(v, ws.y, s1);
        s2 = fmaf(v, ws.z, s2); s3 = fmaf(v, ws.w, s3);
        d0 = fmaf(v, wd.x, d0); d1 = fmaf(v, wd.y, d1);
        d2 = fmaf(v, wd.z, d2); d3 = fmaf(v, wd.w, d3);
    }
#pragma unroll
    for (int o = 16; o; o >>= 1) {
        s0 += __shfl_xor_sync(0xFFFFFFFFu, s0, o);
        s1 += __shfl_xor_sync(0xFFFFFFFFu, s1, o);
        s2 += __shfl_xor_sync(0xFFFFFFFFu, s2, o);
        s3 += __shfl_xor_sync(0xFFFFFFFFu, s3, o);
        d0 += __shfl_xor_sync(0xFFFFFFFFu, d0, o);
        d1 += __shfl_xor_sync(0xFFFFFFFFu, d1, o);
        d2 += __shfl_xor_sync(0xFFFFFFFFu, d2, o);
        d3 += __shfl_xor_sync(0xFFFFFFFFu, d3, o);
    }
    if (lane == 0) {
        *reinterpret_cast<float4*>(&g_as[(size_t)gw * 4]) = make_float4(s0, s1, s2, s3);
        *reinterpret_cast<float4*>(&g_ad[(size_t)gw * 4]) = make_float4(d0, d1, d2, d3);
    }
}

// -------------------- per-node warp softmax ---------------------------------
__global__ void edge_softmax(int N)
{
    int gw   = (blockIdx.x * blockDim.x + threadIdx.x) >> 5;
    int lane = threadIdx.x & 31;
    if (gw >= N) return;
    int beg = g_off[gw], end = g_off[gw + 1];
    float4 D = *reinterpret_cast<const float4*>(g_ad + (size_t)gw * 4);
    float m0 = -1e30f, m1 = -1e30f, m2 = -1e30f, m3 = -1e30f;
    for (int j = beg + lane; j < end; j += 32) {
        int s = g_csrc[j];
        float4 A = *reinterpret_cast<const float4*>(g_as + (size_t)s * 4);
        float v0 = A.x + D.x, v1 = A.y + D.y, v2 = A.z + D.z, v3 = A.w + D.w;
        v0 = v0 > 0.f ? v0 : 0.2f * v0;
        v1 = v1 > 0.f ? v1 : 0.2f * v1;
        v2 = v2 > 0.f ? v2 : 0.2f * v2;
        v3 = v3 > 0.f ? v3 : 0.2f * v3;
        *reinterpret_cast<float4*>(g_alpha + (size_t)j * 4) = make_float4(v0, v1, v2, v3);
        m0 = fmaxf(m0, v0); m1 = fmaxf(m1, v1);
        m2 = fmaxf(m2, v2); m3 = fmaxf(m3, v3);
    }
#pragma unroll
    for (int o = 16; o; o >>= 1) {
        m0 = fmaxf(m0, __shfl_xor_sync(0xFFFFFFFFu, m0, o));
        m1 = fmaxf(m1, __shfl_xor_sync(0xFFFFFFFFu, m1, o));
        m2 = fmaxf(m2, __shfl_xor_sync(0xFFFFFFFFu, m2, o));
        m3 = fmaxf(m3, __shfl_xor_sync(0xFFFFFFFFu, m3, o));
    }
    float s0 = 0.f, s1 = 0.f, s2 = 0.f, s3 = 0.f;
    for (int j = beg + lane; j < end; j += 32) {
        float4 v = *reinterpret_cast<const float4*>(g_alpha + (size_t)j * 4);
        float x0 = expf(v.x - m0), x1 = expf(v.y - m1);
        float x2 = expf(v.z - m2), x3 = expf(v.w - m3);
        *reinterpret_cast<float4*>(g_alpha + (size_t)j * 4) = make_float4(x0, x1, x2, x3);
        s0 += x0; s1 += x1; s2 += x2; s3 += x3;
    }
#pragma unroll
    for (int o = 16; o; o >>= 1) {
        s0 += __shfl_xor_sync(0xFFFFFFFFu, s0, o);
        s1 += __shfl_xor_sync(0xFFFFFFFFu, s1, o);
        s2 += __shfl_xor_sync(0xFFFFFFFFu, s2, o);
        s3 += __shfl_xor_sync(0xFFFFFFFFu, s3, o);
    }
    if (lane == 0)
        *reinterpret_cast<float4*>(g_esum + (size_t)gw * 4) = make_float4(s0, s1, s2, s3);
}

// -------------------- gather aggregates -------------------------------------
__global__ __launch_bounds__(128) void agg1_k(const float* __restrict__ b1, int N)
{
    int n = blockIdx.x;
    if (n >= N) return;
    int c = threadIdx.x;
    int h = c >> 5;
    int beg = g_off[n], end = g_off[n + 1];
    float r = 1.f / (g_esum[(size_t)n * 4 + h] + 1e-16f);
    float acc = 0.f;
    for (int j = beg; j < end; j++) {
        int s = g_csrc[j];
        float w = g_alpha[(size_t)j * 4 + h];
        acc = fmaf(w, g_h1[(size_t)s * 128 + c], acc);
    }
    float v = acc * r + b1[c];
    g_hact[(size_t)n * 128 + c] = v > 0.f ? v : expm1f(v);
}

__global__ __launch_bounds__(128) void agg2n_k(int N)
{
    int n = blockIdx.x;
    if (n >= N) return;
    int k = threadIdx.x;
    int beg = g_off[n], end = g_off[n + 1];
    float a0 = 0.f, a1 = 0.f, a2 = 0.f, a3 = 0.f;
    for (int j = beg; j < end; j++) {
        int s = g_csrc[j];
        float4 al = *reinterpret_cast<const float4*>(g_alpha + (size_t)j * 4);
        float v = g_hact[(size_t)s * 128 + k];
        a0 = fmaf(al.x, v, a0); a1 = fmaf(al.y, v, a1);
        a2 = fmaf(al.z, v, a2); a3 = fmaf(al.w, v, a3);
    }
    float4 es = *reinterpret_cast<const float4*>(g_esum + (size_t)n * 4);
    float* o = g_aggn + (size_t)n * 512;
    o[k]       = a0 * (0.25f / (es.x + 1e-16f));
    o[128 + k] = a1 * (0.25f / (es.y + 1e-16f));
    o[256 + k] = a2 * (0.25f / (es.z + 1e-16f));
    o[384 + k] = a3 * (0.25f / (es.w + 1e-16f));
}

// ---------------------------------------------------------------------------
extern "C" void kernel_launch(void* const* d_in, const int* in_sizes, int n_in,
                              void* d_out, int out_size)
{
    const float* x      = (const float*)d_in[0];
    const int*   eidx   = (const int*)d_in[1];
    const float* W1     = (const float*)d_in[2];
    const float* a_src1 = (const float*)d_in[3];
    const float* a_dst1 = (const float*)d_in[4];
    const float* b1     = (const float*)d_in[5];
    const float* W2     = (const float*)d_in[6];
    const float* a_src2 = (const float*)d_in[7];
    const float* a_dst2 = (const float*)d_in[8];
    const float* b2     = (const float*)d_in[9];
    const float* W_lin  = (const float*)d_in[10];
    const float* b_lin  = (const float*)d_in[11];

    const int N  = in_sizes[0] / 512;
    const int E  = in_sizes[1] / 2;
    const int Et = E + N;

    const int* src = eidx;
    const int* dst = eidx + E;

    float* out = (float*)d_out;
    float* emb = (float*)d_out + (size_t)N * 64;

    float* h1;   cudaGetSymbolAddress((void**)&h1,   g_h1);
    float* hact; cudaGetSymbolAddress((void**)&hact, g_hact);
    float* aggn; cudaGetSymbolAddress((void**)&aggn, g_aggn);
    __nv_bfloat16 *w1h, *w1l, *w2h, *w2l, *wlh, *wll;
    cudaGetSymbolAddress((void**)&w1h, g_W1h); cudaGetSymbolAddress((void**)&w1l, g_W1l);
    cudaGetSymbolAddress((void**)&w2h, g_W2h); cudaGetSymbolAddress((void**)&w2l, g_W2l);
    cudaGetSymbolAddress((void**)&wlh, g_WLh); cudaGetSymbolAddress((void**)&wll, g_WLl);

    const int T = 256;
    dim3 gg(1, (N + 127) / 128);

    int blk_e     = (Et + T - 1) / T;
    int blk_n     = (N + T - 1) / T;
    int blk_alpha = (N * 4 * 32 + T - 1) / T;
    int blk_soft  = (N * 32 + T - 1) / T;
    int NB        = (N + 1023) / 1024;

    // ---- weight prep ----
    split_w<<<(512 * 128 + T - 1) / T, T>>>(W1, w1h, w1l, 512, 128);
    split_w2p<<<(512 * 128 + T - 1) / T, T>>>(W2);
    split_w<<<(128 * 64 + T - 1) / T, T>>>(W_lin, wlh, wll, 128, 64);
    build_wa<<<64, T>>>(W2, a_src2, a_dst2);

    // ---- CSR build ----
    zero_cnt<<<blk_n, T>>>(N);
    hist_k<<<blk_e, T>>>(dst, E, N);
    scan1<<<NB, 1024>>>(N);
    scan2<<<1, 1024>>>(NB);
    scan3<<<blk_n, T>>>(N, Et);
    scatter_k<<<blk_e, T>>>(src, dst, E, N);

    // ---- layer 1 ----
    gemm_bf16x3<<<gg, T>>>(x, w1h, w1l, nullptr, h1, N, 128, 512);
    alpha_kernel<<<blk_alpha, T>>>(h1, a_src1, a_dst1, N, 32);
    edge_softmax<<<blk_soft, T>>>(N);
    agg1_k<<<N, 128>>>(b1, N);

    // ---- layer 2 (deferred W2) ----
    alpha2_kernel<<<blk_soft, T>>>(hact, N);
    edge_softmax<<<blk_soft, T>>>(N);
    agg2n_k<<<N, 128>>>(N);
    gemm_bf16x3<<<gg, T>>>(aggn, w2h, w2l, b2, emb, N, 128, 512);

    // ---- head ----
    gemm_bf16x3<<<gg, T>>>(emb, wlh, wll, b_lin, out, N, 64, 128);
}